// round 2
// baseline (speedup 1.0000x reference)
#include <cuda_runtime.h>

// transforms_blue: per-pixel BGR2GRAY + conditional channel boost, fp32 in/out.
// Layout [B=64, C=3, H=512, W=512]; channel plane = 512*512 = 262144 floats.
// Streaming kernel, unroll x2: 6x LDG.128 + 6x STG.128 per thread.

#define PLANE   262144              // floats per channel plane
#define BATCH_STRIDE (3 * PLANE)
#define PLANE8  (PLANE / 8)         // 32768 float8-groups per plane
#define NGRP    (64 * PLANE8)       // 2,097,152 groups total (divides 256 exactly)

__device__ __forceinline__ float gray_of(float x0, float x1, float x2) {
    float u0 = floorf(x0 * 255.0f);
    float u1 = floorf(x1 * 255.0f);
    float u2 = floorf(x2 * 255.0f);
    return rintf(0.114f * u0 + 0.587f * u1 + 0.299f * u2);  // jnp.round = half-even
}

__device__ __forceinline__ void px(float a, float b, float c,
                                   float& r0, float& r1, float& r2) {
    const float inv255 = 1.0f / 255.0f;
    float gy = gray_of(a, b, c);
    bool m = gy < 128.0f;
    r0 = (m ? gy + 60.0f : gy) * inv255;
    r1 = (m ? gy + 10.0f : gy) * inv255;
    r2 = gy * inv255;
}

__global__ void __launch_bounds__(256) transforms_blue_kernel(
    const float* __restrict__ in, float* __restrict__ out)
{
    unsigned g = blockIdx.x * blockDim.x + threadIdx.x;  // exact grid, no check

    unsigned b    = g >> 15;              // g / PLANE8
    unsigned off  = (g & 32767u) * 8;     // float offset within plane
    unsigned base = b * BATCH_STRIDE + off;

    // Front-batch all 6 independent 128-bit loads (MLP_p1 = 6)
    const float4 a0 = *reinterpret_cast<const float4*>(in + base);
    const float4 a1 = *reinterpret_cast<const float4*>(in + base + 4);
    const float4 b0 = *reinterpret_cast<const float4*>(in + base + PLANE);
    const float4 b1 = *reinterpret_cast<const float4*>(in + base + PLANE + 4);
    const float4 c0 = *reinterpret_cast<const float4*>(in + base + 2 * PLANE);
    const float4 c1 = *reinterpret_cast<const float4*>(in + base + 2 * PLANE + 4);

    float4 o00, o01, o10, o11, o20, o21;

    px(a0.x, b0.x, c0.x, o00.x, o10.x, o20.x);
    px(a0.y, b0.y, c0.y, o00.y, o10.y, o20.y);
    px(a0.z, b0.z, c0.z, o00.z, o10.z, o20.z);
    px(a0.w, b0.w, c0.w, o00.w, o10.w, o20.w);

    px(a1.x, b1.x, c1.x, o01.x, o11.x, o21.x);
    px(a1.y, b1.y, c1.y, o01.y, o11.y, o21.y);
    px(a1.z, b1.z, c1.z, o01.z, o11.z, o21.z);
    px(a1.w, b1.w, c1.w, o01.w, o11.w, o21.w);

    *reinterpret_cast<float4*>(out + base)                 = o00;
    *reinterpret_cast<float4*>(out + base + 4)             = o01;
    *reinterpret_cast<float4*>(out + base + PLANE)         = o10;
    *reinterpret_cast<float4*>(out + base + PLANE + 4)     = o11;
    *reinterpret_cast<float4*>(out + base + 2 * PLANE)     = o20;
    *reinterpret_cast<float4*>(out + base + 2 * PLANE + 4) = o21;
}

extern "C" void kernel_launch(void* const* d_in, const int* in_sizes, int n_in,
                              void* d_out, int out_size) {
    const float* in = (const float*)d_in[0];
    float* out = (float*)d_out;
    const int threads = 256;
    const int blocks = NGRP / threads;   // 8192, exact
    transforms_blue_kernel<<<blocks, threads>>>(in, out);
}

// round 3
// speedup vs baseline: 1.1158x; 1.1158x over previous
#include <cuda_runtime.h>

// transforms_blue: per-pixel BGR2GRAY + conditional channel boost, fp32 in/out.
// Layout [B=64, C=3, H=512, W=512]; channel plane = 512*512 = 262144 floats.
// Unroll x2 with BLOCK-STRIDED groups: every LDG.128/STG.128 is warp-contiguous
// (full 128B-segment coalescing) AND each thread fronts 6 independent loads.

#define PLANE   262144              // floats per channel plane
#define PLANE4  (PLANE / 4)         // 65536 float4-groups per plane
#define BATCH_STRIDE (3 * PLANE)
#define NPIX4   (64 * PLANE4)       // 4,194,304 float4 groups
#define THREADS 256
#define GRPS_PER_BLOCK (2 * THREADS)   // 512, divides PLANE4 exactly

__device__ __forceinline__ float gray_of(float x0, float x1, float x2) {
    float u0 = floorf(x0 * 255.0f);
    float u1 = floorf(x1 * 255.0f);
    float u2 = floorf(x2 * 255.0f);
    return rintf(0.114f * u0 + 0.587f * u1 + 0.299f * u2);  // jnp.round = half-even
}

__device__ __forceinline__ void px(float a, float b, float c,
                                   float& r0, float& r1, float& r2) {
    const float inv255 = 1.0f / 255.0f;
    float gy = gray_of(a, b, c);
    bool m = gy < 128.0f;
    r0 = (m ? gy + 60.0f : gy) * inv255;
    r1 = (m ? gy + 10.0f : gy) * inv255;
    r2 = gy * inv255;
}

__device__ __forceinline__ void do4(const float4& a, const float4& b, const float4& c,
                                    float4& o0, float4& o1, float4& o2) {
    px(a.x, b.x, c.x, o0.x, o1.x, o2.x);
    px(a.y, b.y, c.y, o0.y, o1.y, o2.y);
    px(a.z, b.z, c.z, o0.z, o1.z, o2.z);
    px(a.w, b.w, c.w, o0.w, o1.w, o2.w);
}

__global__ void __launch_bounds__(THREADS) transforms_blue_kernel(
    const float* __restrict__ in, float* __restrict__ out)
{
    // group indices: g0, g1 = g0 + 256 (both within the same plane: 512 | 65536)
    unsigned g0 = blockIdx.x * GRPS_PER_BLOCK + threadIdx.x;

    unsigned b     = g0 >> 16;             // g0 / PLANE4 (g1 same batch & plane)
    unsigned off0  = (g0 & 65535u) * 4;
    unsigned base0 = b * BATCH_STRIDE + off0;
    unsigned base1 = base0 + THREADS * 4;  // g1's float offset

    // 6 independent, fully-coalesced 128-bit loads
    const float4 a0 = *reinterpret_cast<const float4*>(in + base0);
    const float4 b0 = *reinterpret_cast<const float4*>(in + base0 + PLANE);
    const float4 c0 = *reinterpret_cast<const float4*>(in + base0 + 2 * PLANE);
    const float4 a1 = *reinterpret_cast<const float4*>(in + base1);
    const float4 b1 = *reinterpret_cast<const float4*>(in + base1 + PLANE);
    const float4 c1 = *reinterpret_cast<const float4*>(in + base1 + 2 * PLANE);

    float4 o00, o10, o20, o01, o11, o21;
    do4(a0, b0, c0, o00, o10, o20);
    do4(a1, b1, c1, o01, o11, o21);

    *reinterpret_cast<float4*>(out + base0)             = o00;
    *reinterpret_cast<float4*>(out + base0 + PLANE)     = o10;
    *reinterpret_cast<float4*>(out + base0 + 2 * PLANE) = o20;
    *reinterpret_cast<float4*>(out + base1)             = o01;
    *reinterpret_cast<float4*>(out + base1 + PLANE)     = o11;
    *reinterpret_cast<float4*>(out + base1 + 2 * PLANE) = o21;
}

extern "C" void kernel_launch(void* const* d_in, const int* in_sizes, int n_in,
                              void* d_out, int out_size) {
    const float* in = (const float*)d_in[0];
    float* out = (float*)d_out;
    const int blocks = NPIX4 / GRPS_PER_BLOCK;   // 8192, exact
    transforms_blue_kernel<<<blocks, THREADS>>>(in, out);
}

// round 4
// speedup vs baseline: 1.1476x; 1.0285x over previous
#include <cuda_runtime.h>

// transforms_blue: per-pixel BGR2GRAY + conditional channel boost, fp32 in/out.
// Layout [B=64, C=3, H=512, W=512]; channel plane = 512*512 = 262144 floats.
// R0 shape (best measured) + streaming cache hints: zero-reuse data is marked
// evict-first in L2 on both the read and write stream (__ldcs/__stcs).

#define PLANE   262144          // floats per channel plane (512*512)
#define PLANE4  (PLANE / 4)     // 65536 float4 per plane
#define BATCH_STRIDE (3 * PLANE)
#define NPIX4   (64 * PLANE4)   // 4,194,304 float4 pixel-groups (divides 256)
#define THREADS 256

__device__ __forceinline__ float gray_of(float x0, float x1, float x2) {
    float u0 = floorf(x0 * 255.0f);
    float u1 = floorf(x1 * 255.0f);
    float u2 = floorf(x2 * 255.0f);
    return rintf(0.114f * u0 + 0.587f * u1 + 0.299f * u2);  // jnp.round = half-even
}

__device__ __forceinline__ void px(float a, float b, float c,
                                   float& r0, float& r1, float& r2) {
    const float inv255 = 1.0f / 255.0f;
    float gy = gray_of(a, b, c);
    bool m = gy < 128.0f;
    r0 = (m ? gy + 60.0f : gy) * inv255;
    r1 = (m ? gy + 10.0f : gy) * inv255;
    r2 = gy * inv255;
}

__global__ void __launch_bounds__(THREADS) transforms_blue_kernel(
    const float* __restrict__ in, float* __restrict__ out)
{
    unsigned g = blockIdx.x * THREADS + threadIdx.x;   // exact grid, no check

    unsigned b    = g >> 16;            // g / PLANE4
    unsigned off  = (g & 65535u) * 4;   // float offset within plane
    unsigned base = b * BATCH_STRIDE + off;

    // 3 independent, fully-coalesced, streaming 128-bit loads
    const float4 v0 = __ldcs(reinterpret_cast<const float4*>(in + base));
    const float4 v1 = __ldcs(reinterpret_cast<const float4*>(in + base + PLANE));
    const float4 v2 = __ldcs(reinterpret_cast<const float4*>(in + base + 2 * PLANE));

    float4 o0, o1, o2;
    px(v0.x, v1.x, v2.x, o0.x, o1.x, o2.x);
    px(v0.y, v1.y, v2.y, o0.y, o1.y, o2.y);
    px(v0.z, v1.z, v2.z, o0.z, o1.z, o2.z);
    px(v0.w, v1.w, v2.w, o0.w, o1.w, o2.w);

    __stcs(reinterpret_cast<float4*>(out + base),             o0);
    __stcs(reinterpret_cast<float4*>(out + base + PLANE),     o1);
    __stcs(reinterpret_cast<float4*>(out + base + 2 * PLANE), o2);
}

extern "C" void kernel_launch(void* const* d_in, const int* in_sizes, int n_in,
                              void* d_out, int out_size) {
    const float* in = (const float*)d_in[0];
    float* out = (float*)d_out;
    const int blocks = NPIX4 / THREADS;   // 16384, exact
    transforms_blue_kernel<<<blocks, THREADS>>>(in, out);
}

// round 5
// speedup vs baseline: 1.1494x; 1.0015x over previous
#include <cuda_runtime.h>

// transforms_blue: per-pixel BGR2GRAY + conditional channel boost, fp32 in/out.
// Layout [B=64, C=3, H=512, W=512]; channel plane = 512*512 = 262144 floats.
// Best-measured access shape (1 float4-group/thread, fully coalesced, streaming
// cache hints) with 128-thread CTAs: finer scheduling granules to cut the
// cross-CTA L1tex-queue spread that shows up as DRAM-idle tail per wave.

#define PLANE   262144          // floats per channel plane (512*512)
#define PLANE4  (PLANE / 4)     // 65536 float4 per plane
#define BATCH_STRIDE (3 * PLANE)
#define NPIX4   (64 * PLANE4)   // 4,194,304 float4 pixel-groups (divides 128)
#define THREADS 128

__device__ __forceinline__ float gray_of(float x0, float x1, float x2) {
    float u0 = floorf(x0 * 255.0f);
    float u1 = floorf(x1 * 255.0f);
    float u2 = floorf(x2 * 255.0f);
    return rintf(0.114f * u0 + 0.587f * u1 + 0.299f * u2);  // jnp.round = half-even
}

__device__ __forceinline__ void px(float a, float b, float c,
                                   float& r0, float& r1, float& r2) {
    const float inv255 = 1.0f / 255.0f;
    float gy = gray_of(a, b, c);
    bool m = gy < 128.0f;
    r0 = (m ? gy + 60.0f : gy) * inv255;
    r1 = (m ? gy + 10.0f : gy) * inv255;
    r2 = gy * inv255;
}

__global__ void __launch_bounds__(THREADS) transforms_blue_kernel(
    const float* __restrict__ in, float* __restrict__ out)
{
    unsigned g = blockIdx.x * THREADS + threadIdx.x;   // exact grid, no check

    unsigned b    = g >> 16;            // g / PLANE4
    unsigned off  = (g & 65535u) * 4;   // float offset within plane
    unsigned base = b * BATCH_STRIDE + off;

    // 3 independent, fully-coalesced, streaming 128-bit loads
    const float4 v0 = __ldcs(reinterpret_cast<const float4*>(in + base));
    const float4 v1 = __ldcs(reinterpret_cast<const float4*>(in + base + PLANE));
    const float4 v2 = __ldcs(reinterpret_cast<const float4*>(in + base + 2 * PLANE));

    float4 o0, o1, o2;
    px(v0.x, v1.x, v2.x, o0.x, o1.x, o2.x);
    px(v0.y, v1.y, v2.y, o0.y, o1.y, o2.y);
    px(v0.z, v1.z, v2.z, o0.z, o1.z, o2.z);
    px(v0.w, v1.w, v2.w, o0.w, o1.w, o2.w);

    __stcs(reinterpret_cast<float4*>(out + base),             o0);
    __stcs(reinterpret_cast<float4*>(out + base + PLANE),     o1);
    __stcs(reinterpret_cast<float4*>(out + base + 2 * PLANE), o2);
}

extern "C" void kernel_launch(void* const* d_in, const int* in_sizes, int n_in,
                              void* d_out, int out_size) {
    const float* in = (const float*)d_in[0];
    float* out = (float*)d_out;
    const int blocks = NPIX4 / THREADS;   // 32768, exact
    transforms_blue_kernel<<<blocks, THREADS>>>(in, out);
}